// round 15
// baseline (speedup 1.0000x reference)
#include <cuda_runtime.h>

#define LN_EPS   1e-6f
#define INV_TEMP 0.31622776601683794f   // 1/sqrt(10)
#define NRMAX    131072

typedef unsigned long long u64;

// Packed f32x2 helpers (sm_103a)
__device__ __forceinline__ u64 pk2(float lo, float hi) {
    u64 r; asm("mov.b64 %0, {%1, %2};" : "=l"(r) : "f"(lo), "f"(hi)); return r;
}
__device__ __forceinline__ void upk2(float& lo, float& hi, u64 v) {
    asm("mov.b64 {%0, %1}, %2;" : "=f"(lo), "=f"(hi) : "l"(v));
}
#define FMA2(d, a, b, c) \
    asm("fma.rn.f32x2 %0, %1, %2, %3;" : "=l"(d) : "l"(a), "l"(b), "l"(c))

// Sanctioned __device__ scratch.
__device__ float g_qt[(size_t)90 * NRMAX];
__device__ float g_kt[(size_t)90 * NRMAX];
__device__ float g_vt[(size_t)90 * NRMAX];
__device__ float g_mid[(size_t)90 * NRMAX];
__device__ float g_MT[100];   // MT[j*10+i] = sum_o Wq[o,i]*Wk[o,j] / sqrt(10)

// ===========================================================================
// Kernel P: precompute MT.
// ===========================================================================
__global__ void k_precompute(const float* __restrict__ Wq,
                             const float* __restrict__ Wk,
                             float* __restrict__ MT)
{
    int t = threadIdx.x;
    if (t < 100) {
        int j = t / 10, i = t % 10;
        float s = 0.f;
#pragma unroll
        for (int o = 0; o < 10; o++) s = fmaf(Wq[o*10+i], Wk[o*10+j], s);
        MT[j*10 + i] = s * INV_TEMP;
    }
}

// ===========================================================================
// Kernel 0: tiled transpose [B,90] -> [90,B] for q,k,v (blockIdx.y selects).
// ===========================================================================
__global__ __launch_bounds__(256)
void k_transpose3(const float* __restrict__ q_in, const float* __restrict__ k_in,
                  const float* __restrict__ v_in,
                  float* __restrict__ q_out, float* __restrict__ k_out,
                  float* __restrict__ v_out, int nr)
{
    const float* in   = (blockIdx.y == 0) ? q_in  : (blockIdx.y == 1) ? k_in  : v_in;
    float*       outp = (blockIdx.y == 0) ? q_out : (blockIdx.y == 1) ? k_out : v_out;

    __shared__ float ts[90 * 33];
    const int t = threadIdx.x;
    const int row0 = blockIdx.x * 32;
    const size_t base = (size_t)row0 * 90;
    for (int idx = t; idx < 2880; idx += 256) {
        int r = idx / 90, c = idx % 90;
        float v = 0.f;
        if (row0 + r < nr) v = in[base + idx];
        ts[c * 33 + r] = v;
    }
    __syncthreads();
    for (int idx = t; idx < 2880; idx += 256) {
        int c = idx >> 5, r = idx & 31;
        if (row0 + r < nr)
            outp[(size_t)c * nr + row0 + r] = ts[c * 33 + r];
    }
}

// ===========================================================================
// Kernel 1: phases 1+2. One thread per (row, branch).
// MT-fused attention; PFF30 GEMVs use packed fma.rn.f32x2.
// ===========================================================================
#define K1_WQMT 0      // 100
#define K1_WV   100    // 100
#define K1_GM   200    // 10
#define K1_BM   212    // 10
#define K1_B1   224    // 30
#define K1_B2   256    // 30
#define K1_GP   288    // 30
#define K1_BP   320    // 30
#define K1_W1T  352    // W1^T padded: [i*32+j], 960
#define K1_W2R  1312   // W2 row-padded: [j*32+i], 960
#define K1_TOT  2272
#define SX_STRIDE 33

__device__ __forceinline__ void proj3x10(float o[30], const float in[30],
                                         const float* __restrict__ W)
{
#pragma unroll
    for (int oo = 0; oo < 10; oo++) {
        const float2* wp = reinterpret_cast<const float2*>(W + oo * 10);
        float w[10];
#pragma unroll
        for (int p = 0; p < 5; p++) { float2 u = wp[p]; w[2*p] = u.x; w[2*p+1] = u.y; }
#pragma unroll
        for (int s = 0; s < 3; s++) {
            float a0 = 0.f, a1 = 0.f;
#pragma unroll
            for (int i = 0; i < 5; i++) {
                a0 = fmaf(in[s*10+i],   w[i],   a0);
                a1 = fmaf(in[s*10+5+i], w[5+i], a1);
            }
            o[s*10+oo] = a0 + a1;
        }
    }
}

__device__ __forceinline__ void attn_scores_raw(float att[9], const float qm[30],
                                                const float kb[30])
{
#pragma unroll
    for (int s = 0; s < 3; s++)
#pragma unroll
        for (int tt = 0; tt < 3; tt++) {
            float a0 = 0.f, a1 = 0.f;
#pragma unroll
            for (int d = 0; d < 5; d++) {
                a0 = fmaf(qm[s*10+d],   kb[tt*10+d],   a0);
                a1 = fmaf(qm[s*10+5+d], kb[tt*10+5+d], a1);
            }
            att[s*3+tt] = a0 + a1;
        }
}

__device__ __forceinline__ void attn_combine_ln(float* __restrict__ xs,
                                                const float att[9],
                                                const float vh[30],
                                                const float qb[30],
                                                const float* __restrict__ smw)
{
#pragma unroll
    for (int s = 0; s < 3; s++) {
        float t10[10];
        float m = 0.f;
#pragma unroll
        for (int d = 0; d < 10; d++) {
            float a = qb[s*10+d];
            a = fmaf(att[s*3+0], vh[d],    a);
            a = fmaf(att[s*3+1], vh[10+d], a);
            a = fmaf(att[s*3+2], vh[20+d], a);
            t10[d] = a; m += a;
        }
        m *= 0.1f;
        float vv0 = 0.f, vv1 = 0.f;
#pragma unroll
        for (int d = 0; d < 5; d++) {
            float d0 = t10[d] - m, d1 = t10[5+d] - m;
            vv0 = fmaf(d0, d0, vv0);
            vv1 = fmaf(d1, d1, vv1);
        }
        float r = rsqrtf(fmaf(vv0 + vv1, 0.1f, LN_EPS));
#pragma unroll
        for (int d = 0; d < 10; d++)
            xs[s*10+d] = fmaf((t10[d] - m) * r, smw[K1_GM+d], smw[K1_BM+d]);
    }
}

// PFF(30) on a 30-float SMEM slice, packed f32x2 GEMVs.
__device__ __forceinline__ void pff30_smem(float* __restrict__ xs,
                                           const float* __restrict__ smw)
{
    u64 h2[16];   // h[2k], h[2k+1] packed
    {
        const float2* b1p = reinterpret_cast<const float2*>(smw + K1_B1);
#pragma unroll
        for (int j2 = 0; j2 < 15; j2++) { float2 b = b1p[j2]; h2[j2] = pk2(b.x, b.y); }
        h2[15] = 0ull;   // pads
    }
#pragma unroll 1
    for (int i = 0; i < 30; i++) {
        float xi = xs[i];
        u64 xi2 = pk2(xi, xi);
        const ulonglong2* wr = reinterpret_cast<const ulonglong2*>(smw + K1_W1T + i*32);
#pragma unroll
        for (int j8 = 0; j8 < 8; j8++) {
            ulonglong2 ww = wr[j8];
            FMA2(h2[2*j8],   xi2, ww.x, h2[2*j8]);
            FMA2(h2[2*j8+1], xi2, ww.y, h2[2*j8+1]);
        }
    }
    // ReLU (packed -> scalar -> packed)
#pragma unroll
    for (int j2 = 0; j2 < 16; j2++) {
        float lo, hi; upk2(lo, hi, h2[j2]);
        h2[j2] = pk2(fmaxf(lo, 0.f), fmaxf(hi, 0.f));
    }
    float mean = 0.f;
#pragma unroll 1
    for (int j = 0; j < 30; j++) {
        u64 p0 = pk2(smw[K1_B2+j], 0.f), p1 = 0ull, p2 = 0ull, p3 = 0ull;
        const ulonglong2* wr = reinterpret_cast<const ulonglong2*>(smw + K1_W2R + j*32);
#pragma unroll
        for (int i8 = 0; i8 < 4; i8++) {
            ulonglong2 wa = wr[2*i8], wb = wr[2*i8+1];
            FMA2(p0, h2[4*i8+0], wa.x, p0);
            FMA2(p1, h2[4*i8+1], wa.y, p1);
            FMA2(p2, h2[4*i8+2], wb.x, p2);
            FMA2(p3, h2[4*i8+3], wb.y, p3);
        }
        float l0, u0, l1, u1, l2, u2, l3, u3;
        upk2(l0, u0, p0); upk2(l1, u1, p1); upk2(l2, u2, p2); upk2(l3, u3, p3);
        float a = ((l0 + u0) + (l1 + u1)) + ((l2 + u2) + (l3 + u3)) + xs[j];
        xs[j] = a;
        mean += a;
    }
    mean *= (1.f / 30.f);
    float v0 = 0.f, v1 = 0.f;
#pragma unroll 1
    for (int j = 0; j < 30; j += 2) {
        float d0 = xs[j] - mean, d1 = xs[j+1] - mean;
        v0 = fmaf(d0, d0, v0);
        v1 = fmaf(d1, d1, v1);
    }
    float r = rsqrtf(fmaf(v0 + v1, 1.f / 30.f, LN_EPS));
#pragma unroll 1
    for (int j = 0; j < 30; j++)
        xs[j] = fmaf((xs[j] - mean) * r, smw[K1_GP+j], smw[K1_BP+j]);
}

__global__ __launch_bounds__(256, 2)
void k_phase12(const float* __restrict__ gq, const float* __restrict__ gk,
               const float* __restrict__ gv,
               const float* __restrict__ MT, const float* __restrict__ Wv,
               const float* __restrict__ gm, const float* __restrict__ bm,
               const float* __restrict__ W1, const float* __restrict__ b1,
               const float* __restrict__ W2, const float* __restrict__ b2,
               const float* __restrict__ gp, const float* __restrict__ bp,
               float* __restrict__ xout, int nr)
{
    __shared__ float smw[K1_TOT];
    __shared__ float sx[256 * SX_STRIDE];
    {
        int t = threadIdx.x;
        for (int i = t; i < 100; i += 256) { smw[K1_WQMT+i] = MT[i]; smw[K1_WV+i] = Wv[i]; }
        if (t < 10) { smw[K1_GM+t] = gm[t]; smw[K1_BM+t] = bm[t]; }
        if (t >= 32 && t < 62) {
            int j = t - 32;
            smw[K1_B1+j] = b1[j]; smw[K1_B2+j] = b2[j]; smw[K1_GP+j] = gp[j]; smw[K1_BP+j] = bp[j];
        }
        for (int i = t; i < 1920; i += 256) smw[K1_W1T + i] = 0.f;
        __syncthreads();
        for (int idx = t; idx < 900; idx += 256) {
            int j = idx / 30, i = idx % 30;
            smw[K1_W1T + i*32 + j] = W1[idx];
            smw[K1_W2R + j*32 + i] = W2[idx];
        }
    }
    __syncthreads();

    const int row = blockIdx.x * 256 + threadIdx.x;
    const int b   = blockIdx.y;
    if (row >= nr) return;

    float* __restrict__ myx = sx + threadIdx.x * SX_STRIDE;

    // ---- stage 1: MHA(q,k,v) ----
    {
        const float* qc = gq + (size_t)b * 30 * nr + row;
        float qb[30];
#pragma unroll
        for (int d = 0; d < 30; d++) qb[d] = qc[(size_t)d * nr];

        float qm[30];
        proj3x10(qm, qb, smw + K1_WQMT);

        float att[9];
        {
            const float* kc = gk + (size_t)b * 30 * nr + row;
            float kb[30];
#pragma unroll
            for (int d = 0; d < 30; d++) kb[d] = kc[(size_t)d * nr];
            attn_scores_raw(att, qm, kb);
        }

        float vh[30];
        {
            const float* vc = gv + (size_t)b * 30 * nr + row;
            float tb[30];
#pragma unroll
            for (int d = 0; d < 30; d++) tb[d] = vc[(size_t)d * nr];
            proj3x10(vh, tb, smw + K1_WV);
        }

        attn_combine_ln(myx, att, vh, qb, smw);
    }
    pff30_smem(myx, smw);

    // ---- stage 2: MHA(x,x,x) ----
    {
        float qb[30];
#pragma unroll
        for (int d = 0; d < 30; d++) qb[d] = myx[d];
        float qm[30];
        proj3x10(qm, qb, smw + K1_WQMT);
        float att[9];
        attn_scores_raw(att, qm, qb);
        float vh[30];
        proj3x10(vh, qb, smw + K1_WV);
        attn_combine_ln(myx, att, vh, qb, smw);
    }
    pff30_smem(myx, smw);

#pragma unroll 1
    for (int d = 0; d < 30; d++)
        xout[(size_t)(b * 30 + d) * nr + row] = myx[d];
}

// ===========================================================================
// Kernel 2: PFF(90) + classifier + softmax.
// 512 threads = 16 warps; warp = 8 j-groups x 4 clusters x 2 rows.
// Thread owns 12 outputs x 2 rows. Same 128-row tile / SMEM as before.
// ===========================================================================
#define S3_W1   0        // W1p^T: [i*96 + j], 8640 (pads zero)
#define S3_W2   8640     // W2p^T: [i*96 + j], 8640
#define S3_WC1  17280    // Wc1^T: [i*48 + j], 4320
#define S3_B1P  21600    // 96
#define S3_B2P  21696    // 96
#define S3_G1   21792    // 96
#define S3_BB1  21888    // 96
#define S3_BC1  21984    // 48
#define S3_WC2  22032    // [c*48 + j], 144
#define S3_BC2  22176    // 4
#define S3_X    22180    // x tile: [96][stride 132] = 12672
#define S3_H    34852    // h tile: [96][stride 132] = 12672
#define S3_TOT  47524    // floats = 190096 bytes

#define S3_RS   132
#define NT3     512

__global__ __launch_bounds__(NT3)
void k_phase3(const float* __restrict__ xin,
              const float* __restrict__ W1p, const float* __restrict__ b1p,
              const float* __restrict__ W2p, const float* __restrict__ b2p,
              const float* __restrict__ g1,  const float* __restrict__ bb1,
              const float* __restrict__ Wc1, const float* __restrict__ bc1,
              const float* __restrict__ Wc2, const float* __restrict__ bc2,
              float* __restrict__ out, int nr)
{
    extern __shared__ float sm[];
    const int t = threadIdx.x;

    for (int i = t; i < S3_X; i += NT3) sm[i] = 0.f;
    __syncthreads();
    for (int idx = t; idx < 8100; idx += NT3) {
        int j = idx / 90, i = idx % 90;
        sm[S3_W1 + i*96 + j] = W1p[idx];
        sm[S3_W2 + i*96 + j] = W2p[idx];
    }
    for (int idx = t; idx < 4050; idx += NT3) {
        int j = idx / 90, i = idx % 90;
        sm[S3_WC1 + i*48 + j] = Wc1[idx];
    }
    for (int i = t; i < 90; i += NT3) {
        sm[S3_B1P+i] = b1p[i]; sm[S3_B2P+i] = b2p[i];
        sm[S3_G1+i]  = g1[i];  sm[S3_BB1+i] = bb1[i];
    }
    for (int i = t; i < 45;  i += NT3) sm[S3_BC1 + i] = bc1[i];
    for (int i = t; i < 135; i += NT3) { int c = i / 45, j = i % 45; sm[S3_WC2 + c*48 + j] = Wc2[i]; }
    for (int i = t; i < 3;   i += NT3) sm[S3_BC2 + i] = bc2[i];

    const int row0 = blockIdx.x * 128;

    for (int idx = t; idx < 96 * 128; idx += NT3) {
        int j = idx >> 7, rr = idx & 127;
        float v = 0.f;
        if (j < 90) {
            int gr = row0 + rr;
            if (gr < nr) v = xin[(size_t)j * nr + gr];
        }
        sm[S3_X + j * S3_RS + rr] = v;
    }
    __syncthreads();

    const int lane = t & 31, w = t >> 5;        // 16 warps
    const int g = lane >> 2;                     // j-group 0..7
    const int c = lane & 3;                      // row cluster 0..3
    const int rbase = w * 8 + c * 2;             // this thread's 2 tile-rows
    const float* __restrict__ xt = sm + S3_X;
    float*       __restrict__ ht = sm + S3_H;

    float acc[24];   // acc[q*2 + rho]

    // ---- GEMV1: h = relu(W1p x + b1p) ----
#pragma unroll
    for (int q = 0; q < 12; q++) {
        float bb = sm[S3_B1P + g*12 + q];
        acc[q*2+0] = bb; acc[q*2+1] = bb;
    }
    {
        const float* wbase = sm + S3_W1 + g * 12;
#pragma unroll 3
        for (int i = 0; i < 90; i++) {
            float2 xv = *reinterpret_cast<const float2*>(xt + i * S3_RS + rbase);
            const float4* wv = reinterpret_cast<const float4*>(wbase + i * 96);
            float4 w0 = wv[0], w1 = wv[1], w2 = wv[2];
            float wq[12] = { w0.x, w0.y, w0.z, w0.w,
                             w1.x, w1.y, w1.z, w1.w,
                             w2.x, w2.y, w2.z, w2.w };
#pragma unroll
            for (int q = 0; q < 12; q++) {
                acc[q*2+0] = fmaf(wq[q], xv.x, acc[q*2+0]);
                acc[q*2+1] = fmaf(wq[q], xv.y, acc[q*2+1]);
            }
        }
    }
#pragma unroll
    for (int q = 0; q < 12; q++) {
        int j = g*12 + q;
        float2 hv;
        hv.x = fmaxf(acc[q*2+0], 0.f);
        hv.y = fmaxf(acc[q*2+1], 0.f);
        *reinterpret_cast<float2*>(ht + j * S3_RS + rbase) = hv;
    }
    __syncwarp();   // warp w owns rows w*8..w*8+7 entirely

    // ---- GEMV2: x2 = x + W2p h + b2p ----
#pragma unroll
    for (int q = 0; q < 12; q++) {
        float bb = sm[S3_B2P + g*12 + q];
        acc[q*2+0] = bb; acc[q*2+1] = bb;
    }
    {
        const float* wbase = sm + S3_W2 + g * 12;
#pragma unroll 3
        for (int i = 0; i < 90; i++) {
            float2 hv = *reinterpret_cast<const float2*>(ht + i * S3_RS + rbase);
            const float4* wv = reinterpret_cast<const float4*>(wbase + i * 96);
            float4 w0 = wv[0], w1 = wv[1], w2 = wv[2];
            float wq[12] = { w0.x, w0.y, w0.z, w0.w,
                             w1.x, w1.y, w1.z, w1.w,
                             w2.x, w2.y, w2.z, w2.w };
#pragma unroll
            for (int q = 0; q < 12; q++) {
                acc[q*2+0] = fmaf(wq[q], hv.x, acc[q*2+0]);
                acc[q*2+1] = fmaf(wq[q], hv.y, acc[q*2+1]);
            }
        }
    }
    float s0 = 0.f, s1 = 0.f;
#pragma unroll
    for (int q = 0; q < 12; q++) {
        int j = g*12 + q;
        float2 xv = *reinterpret_cast<const float2*>(xt + j * S3_RS + rbase);
        acc[q*2+0] += xv.x; acc[q*2+1] += xv.y;
        s0 += acc[q*2+0]; s1 += acc[q*2+1];
    }
#pragma unroll
    for (int m = 4; m < 32; m <<= 1) {
        s0 += __shfl_xor_sync(0xffffffffu, s0, m);
        s1 += __shfl_xor_sync(0xffffffffu, s1, m);
    }
    float m0 = s0 * (1.f/90.f), m1 = s1 * (1.f/90.f);
    float v0 = 0.f, v1 = 0.f;
#pragma unroll
    for (int q = 0; q < 12; q++) {
        int j = g*12 + q;
        if (j < 90) {
            float d0 = acc[q*2+0]-m0, d1 = acc[q*2+1]-m1;
            v0 = fmaf(d0,d0,v0); v1 = fmaf(d1,d1,v1);
        }
    }
#pragma unroll
    for (int m = 4; m < 32; m <<= 1) {
        v0 += __shfl_xor_sync(0xffffffffu, v0, m);
        v1 += __shfl_xor_sync(0xffffffffu, v1, m);
    }
    float r0 = rsqrtf(fmaf(v0, 1.f/90.f, LN_EPS));
    float r1 = rsqrtf(fmaf(v1, 1.f/90.f, LN_EPS));

    __syncwarp();
#pragma unroll
    for (int q = 0; q < 12; q++) {
        int j = g*12 + q;
        float2 xn;
        if (j < 90) {
            float gg = sm[S3_G1 + j], bb = sm[S3_BB1 + j];
            xn.x = fmaf((acc[q*2+0]-m0)*r0, gg, bb);
            xn.y = fmaf((acc[q*2+1]-m1)*r1, gg, bb);
        } else {
            xn.x = 0.f; xn.y = 0.f;
        }
        *reinterpret_cast<float2*>(ht + j * S3_RS + rbase) = xn;
    }
    __syncwarp();

    // ---- classifier: lane owns j = g*6..g*6+5, 2 rows ----
    float cacc[12];
#pragma unroll
    for (int q = 0; q < 6; q++) {
        float bb = sm[S3_BC1 + g*6 + q];
        cacc[q*2+0] = bb; cacc[q*2+1] = bb;
    }
    {
        const float* wbase = sm + S3_WC1 + g * 6;
#pragma unroll 3
        for (int i = 0; i < 90; i++) {
            float2 xv = *reinterpret_cast<const float2*>(ht + i * S3_RS + rbase);
            float2 wa = *reinterpret_cast<const float2*>(wbase + i * 48);
            float2 wb = *reinterpret_cast<const float2*>(wbase + i * 48 + 2);
            float2 wc = *reinterpret_cast<const float2*>(wbase + i * 48 + 4);
            float wq[6] = { wa.x, wa.y, wb.x, wb.y, wc.x, wc.y };
#pragma unroll
            for (int q = 0; q < 6; q++) {
                cacc[q*2+0] = fmaf(wq[q], xv.x, cacc[q*2+0]);
                cacc[q*2+1] = fmaf(wq[q], xv.y, cacc[q*2+1]);
            }
        }
    }
    float lg[6];     // lg[cc*2 + rho]
#pragma unroll
    for (int i = 0; i < 6; i++) lg[i] = 0.f;
#pragma unroll
    for (int q = 0; q < 6; q++) {
        int j = g*6 + q;
        float w0 = sm[S3_WC2 + j];
        float w1 = sm[S3_WC2 + 48 + j];
        float w2 = sm[S3_WC2 + 96 + j];
#pragma unroll
        for (int rho = 0; rho < 2; rho++) {
            float a = fmaxf(cacc[q*2+rho], 0.f);
            lg[0*2+rho] = fmaf(a, w0, lg[0*2+rho]);
            lg[1*2+rho] = fmaf(a, w1, lg[1*2+rho]);
            lg[2*2+rho] = fmaf(a, w2, lg[2*2+rho]);
        }
    }
#pragma unroll
    for (int m = 4; m < 32; m <<= 1)
#pragma unroll
        for (int i = 0; i < 6; i++)
            lg[i] += __shfl_xor_sync(0xffffffffu, lg[i], m);
    float bc20 = sm[S3_BC2+0], bc21 = sm[S3_BC2+1], bc22 = sm[S3_BC2+2];
#pragma unroll
    for (int rho = 0; rho < 2; rho++) {
        float l0 = lg[rho] + bc20, l1 = lg[2+rho] + bc21, l2 = lg[4+rho] + bc22;
        float mm = fmaxf(l0, fmaxf(l1, l2));
        float e0 = __expf(l0 - mm), e1 = __expf(l1 - mm), e2 = __expf(l2 - mm);
        float inv = __frcp_rn(e0 + e1 + e2);
        int row = row0 + rbase + rho;
        if (row < nr && g < 3) {
            float e = (g == 0) ? e0 : (g == 1) ? e1 : e2;
            out[(size_t)row * 3 + g] = e * inv;
        }
    }
}

// ===========================================================================
extern "C" void kernel_launch(void* const* d_in, const int* in_sizes, int n_in,
                              void* d_out, int out_size)
{
    const float* A[24];
    for (int i = 0; i < 24; i++) A[i] = (const float*)d_in[i];

    int nr = in_sizes[0] / 90;
    if (nr > NRMAX) nr = NRMAX;

    float *qt, *kt, *vt, *mid, *MT;
    cudaGetSymbolAddress((void**)&qt,  g_qt);
    cudaGetSymbolAddress((void**)&kt,  g_kt);
    cudaGetSymbolAddress((void**)&vt,  g_vt);
    cudaGetSymbolAddress((void**)&mid, g_mid);
    cudaGetSymbolAddress((void**)&MT,  g_MT);

    k_precompute<<<1, 128>>>(A[3], A[4], MT);

    int btr = (nr + 31) / 32;
    dim3 g0(btr, 3);
    k_transpose3<<<g0, 256>>>(A[0], A[1], A[2], qt, kt, vt, nr);

    int bx = (nr + 255) / 256;
    dim3 g1(bx, 3);
    k_phase12<<<g1, 256>>>(qt, kt, vt,
                           MT, A[5],
                           A[6], A[7],
                           A[8], A[9], A[10], A[11],
                           A[12], A[13],
                           mid, nr);

    int bx3 = (nr + 127) / 128;
    cudaFuncSetAttribute(k_phase3, cudaFuncAttributeMaxDynamicSharedMemorySize,
                         S3_TOT * (int)sizeof(float));
    k_phase3<<<bx3, NT3, S3_TOT * sizeof(float)>>>(
        mid,
        A[14], A[15], A[16], A[17],
        A[18], A[19],
        A[20], A[21], A[22], A[23],
        (float*)d_out, nr);
}

// round 16
// speedup vs baseline: 1.4387x; 1.4387x over previous
#include <cuda_runtime.h>

#define LN_EPS   1e-6f
#define INV_TEMP 0.31622776601683794f   // 1/sqrt(10)
#define NRMAX    131072

typedef unsigned long long u64;

// Packed f32x2 helpers (sm_103a)
__device__ __forceinline__ u64 pk2(float lo, float hi) {
    u64 r; asm("mov.b64 %0, {%1, %2};" : "=l"(r) : "f"(lo), "f"(hi)); return r;
}
__device__ __forceinline__ void upk2(float& lo, float& hi, u64 v) {
    asm("mov.b64 {%0, %1}, %2;" : "=f"(lo), "=f"(hi) : "l"(v));
}
#define FMA2(d, a, b, c) \
    asm("fma.rn.f32x2 %0, %1, %2, %3;" : "=l"(d) : "l"(a), "l"(b), "l"(c))

// Sanctioned __device__ scratch.
__device__ float g_qt[(size_t)90 * NRMAX];
__device__ float g_kt[(size_t)90 * NRMAX];
__device__ float g_vt[(size_t)90 * NRMAX];
__device__ float g_mid[(size_t)90 * NRMAX];
__device__ float g_MT[100];

// ===========================================================================
// Kernel P: precompute MT = Wq^T Wk / sqrt(10) (torch-Linear layout).
// ===========================================================================
__global__ void k_precompute(const float* __restrict__ Wq,
                             const float* __restrict__ Wk,
                             float* __restrict__ MT)
{
    int t = threadIdx.x;
    if (t < 100) {
        int j = t / 10, i = t % 10;
        float s = 0.f;
#pragma unroll
        for (int o = 0; o < 10; o++) s = fmaf(Wq[o*10+i], Wk[o*10+j], s);
        MT[j*10 + i] = s * INV_TEMP;
    }
}

// ===========================================================================
// Kernel 0: tiled transpose [B,90] -> [90,B] for q,k,v.
// ===========================================================================
__global__ __launch_bounds__(256)
void k_transpose3(const float* __restrict__ q_in, const float* __restrict__ k_in,
                  const float* __restrict__ v_in,
                  float* __restrict__ q_out, float* __restrict__ k_out,
                  float* __restrict__ v_out, int nr)
{
    const float* in   = (blockIdx.y == 0) ? q_in  : (blockIdx.y == 1) ? k_in  : v_in;
    float*       outp = (blockIdx.y == 0) ? q_out : (blockIdx.y == 1) ? k_out : v_out;

    __shared__ float ts[90 * 33];
    const int t = threadIdx.x;
    const int row0 = blockIdx.x * 32;
    const size_t base = (size_t)row0 * 90;
    for (int idx = t; idx < 2880; idx += 256) {
        int r = idx / 90, c = idx % 90;
        float v = 0.f;
        if (row0 + r < nr) v = in[base + idx];
        ts[c * 33 + r] = v;
    }
    __syncthreads();
    for (int idx = t; idx < 2880; idx += 256) {
        int c = idx >> 5, r = idx & 31;
        if (row0 + r < nr)
            outp[(size_t)c * nr + row0 + r] = ts[c * 33 + r];
    }
}

// ===========================================================================
// Kernel 1: phases 1+2 (unchanged from R15 — its best measured variant).
// ===========================================================================
#define K1_WQMT 0
#define K1_WV   100
#define K1_GM   200
#define K1_BM   212
#define K1_B1   224
#define K1_B2   256
#define K1_GP   288
#define K1_BP   320
#define K1_W1T  352
#define K1_W2R  1312
#define K1_TOT  2272
#define SX_STRIDE 33

__device__ __forceinline__ void proj3x10(float o[30], const float in[30],
                                         const float* __restrict__ W)
{
#pragma unroll
    for (int oo = 0; oo < 10; oo++) {
        const float2* wp = reinterpret_cast<const float2*>(W + oo * 10);
        float w[10];
#pragma unroll
        for (int p = 0; p < 5; p++) { float2 u = wp[p]; w[2*p] = u.x; w[2*p+1] = u.y; }
#pragma unroll
        for (int s = 0; s < 3; s++) {
            float a0 = 0.f, a1 = 0.f;
#pragma unroll
            for (int i = 0; i < 5; i++) {
                a0 = fmaf(in[s*10+i],   w[i],   a0);
                a1 = fmaf(in[s*10+5+i], w[5+i], a1);
            }
            o[s*10+oo] = a0 + a1;
        }
    }
}

__device__ __forceinline__ void attn_scores_raw(float att[9], const float qm[30],
                                                const float kb[30])
{
#pragma unroll
    for (int s = 0; s < 3; s++)
#pragma unroll
        for (int tt = 0; tt < 3; tt++) {
            float a0 = 0.f, a1 = 0.f;
#pragma unroll
            for (int d = 0; d < 5; d++) {
                a0 = fmaf(qm[s*10+d],   kb[tt*10+d],   a0);
                a1 = fmaf(qm[s*10+5+d], kb[tt*10+5+d], a1);
            }
            att[s*3+tt] = a0 + a1;
        }
}

__device__ __forceinline__ void attn_combine_ln(float* __restrict__ xs,
                                                const float att[9],
                                                const float vh[30],
                                                const float qb[30],
                                                const float* __restrict__ smw)
{
#pragma unroll
    for (int s = 0; s < 3; s++) {
        float t10[10];
        float m = 0.f;
#pragma unroll
        for (int d = 0; d < 10; d++) {
            float a = qb[s*10+d];
            a = fmaf(att[s*3+0], vh[d],    a);
            a = fmaf(att[s*3+1], vh[10+d], a);
            a = fmaf(att[s*3+2], vh[20+d], a);
            t10[d] = a; m += a;
        }
        m *= 0.1f;
        float vv0 = 0.f, vv1 = 0.f;
#pragma unroll
        for (int d = 0; d < 5; d++) {
            float d0 = t10[d] - m, d1 = t10[5+d] - m;
            vv0 = fmaf(d0, d0, vv0);
            vv1 = fmaf(d1, d1, vv1);
        }
        float r = rsqrtf(fmaf(vv0 + vv1, 0.1f, LN_EPS));
#pragma unroll
        for (int d = 0; d < 10; d++)
            xs[s*10+d] = fmaf((t10[d] - m) * r, smw[K1_GM+d], smw[K1_BM+d]);
    }
}

__device__ __forceinline__ void pff30_smem(float* __restrict__ xs,
                                           const float* __restrict__ smw)
{
    u64 h2[16];
    {
        const float2* b1p = reinterpret_cast<const float2*>(smw + K1_B1);
#pragma unroll
        for (int j2 = 0; j2 < 15; j2++) { float2 b = b1p[j2]; h2[j2] = pk2(b.x, b.y); }
        h2[15] = 0ull;
    }
#pragma unroll 1
    for (int i = 0; i < 30; i++) {
        float xi = xs[i];
        u64 xi2 = pk2(xi, xi);
        const ulonglong2* wr = reinterpret_cast<const ulonglong2*>(smw + K1_W1T + i*32);
#pragma unroll
        for (int j8 = 0; j8 < 8; j8++) {
            ulonglong2 ww = wr[j8];
            FMA2(h2[2*j8],   xi2, ww.x, h2[2*j8]);
            FMA2(h2[2*j8+1], xi2, ww.y, h2[2*j8+1]);
        }
    }
#pragma unroll
    for (int j2 = 0; j2 < 16; j2++) {
        float lo, hi; upk2(lo, hi, h2[j2]);
        h2[j2] = pk2(fmaxf(lo, 0.f), fmaxf(hi, 0.f));
    }
    float mean = 0.f;
#pragma unroll 1
    for (int j = 0; j < 30; j++) {
        u64 p0 = pk2(smw[K1_B2+j], 0.f), p1 = 0ull, p2 = 0ull, p3 = 0ull;
        const ulonglong2* wr = reinterpret_cast<const ulonglong2*>(smw + K1_W2R + j*32);
#pragma unroll
        for (int i8 = 0; i8 < 4; i8++) {
            ulonglong2 wa = wr[2*i8], wb = wr[2*i8+1];
            FMA2(p0, h2[4*i8+0], wa.x, p0);
            FMA2(p1, h2[4*i8+1], wa.y, p1);
            FMA2(p2, h2[4*i8+2], wb.x, p2);
            FMA2(p3, h2[4*i8+3], wb.y, p3);
        }
        float l0, u0, l1, u1, l2, u2, l3, u3;
        upk2(l0, u0, p0); upk2(l1, u1, p1); upk2(l2, u2, p2); upk2(l3, u3, p3);
        float a = ((l0 + u0) + (l1 + u1)) + ((l2 + u2) + (l3 + u3)) + xs[j];
        xs[j] = a;
        mean += a;
    }
    mean *= (1.f / 30.f);
    float v0 = 0.f, v1 = 0.f;
#pragma unroll 1
    for (int j = 0; j < 30; j += 2) {
        float d0 = xs[j] - mean, d1 = xs[j+1] - mean;
        v0 = fmaf(d0, d0, v0);
        v1 = fmaf(d1, d1, v1);
    }
    float r = rsqrtf(fmaf(v0 + v1, 1.f / 30.f, LN_EPS));
#pragma unroll 1
    for (int j = 0; j < 30; j++)
        xs[j] = fmaf((xs[j] - mean) * r, smw[K1_GP+j], smw[K1_BP+j]);
}

__global__ __launch_bounds__(256, 2)
void k_phase12(const float* __restrict__ gq, const float* __restrict__ gk,
               const float* __restrict__ gv,
               const float* __restrict__ MT, const float* __restrict__ Wv,
               const float* __restrict__ gm, const float* __restrict__ bm,
               const float* __restrict__ W1, const float* __restrict__ b1,
               const float* __restrict__ W2, const float* __restrict__ b2,
               const float* __restrict__ gp, const float* __restrict__ bp,
               float* __restrict__ xout, int nr)
{
    __shared__ float smw[K1_TOT];
    __shared__ float sx[256 * SX_STRIDE];
    {
        int t = threadIdx.x;
        for (int i = t; i < 100; i += 256) { smw[K1_WQMT+i] = MT[i]; smw[K1_WV+i] = Wv[i]; }
        if (t < 10) { smw[K1_GM+t] = gm[t]; smw[K1_BM+t] = bm[t]; }
        if (t >= 32 && t < 62) {
            int j = t - 32;
            smw[K1_B1+j] = b1[j]; smw[K1_B2+j] = b2[j]; smw[K1_GP+j] = gp[j]; smw[K1_BP+j] = bp[j];
        }
        for (int i = t; i < 1920; i += 256) smw[K1_W1T + i] = 0.f;
        __syncthreads();
        for (int idx = t; idx < 900; idx += 256) {
            int j = idx / 30, i = idx % 30;
            smw[K1_W1T + i*32 + j] = W1[idx];
            smw[K1_W2R + j*32 + i] = W2[idx];
        }
    }
    __syncthreads();

    const int row = blockIdx.x * 256 + threadIdx.x;
    const int b   = blockIdx.y;
    if (row >= nr) return;

    float* __restrict__ myx = sx + threadIdx.x * SX_STRIDE;

    {
        const float* qc = gq + (size_t)b * 30 * nr + row;
        float qb[30];
#pragma unroll
        for (int d = 0; d < 30; d++) qb[d] = qc[(size_t)d * nr];

        float qm[30];
        proj3x10(qm, qb, smw + K1_WQMT);

        float att[9];
        {
            const float* kc = gk + (size_t)b * 30 * nr + row;
            float kb[30];
#pragma unroll
            for (int d = 0; d < 30; d++) kb[d] = kc[(size_t)d * nr];
            attn_scores_raw(att, qm, kb);
        }

        float vh[30];
        {
            const float* vc = gv + (size_t)b * 30 * nr + row;
            float tb[30];
#pragma unroll
            for (int d = 0; d < 30; d++) tb[d] = vc[(size_t)d * nr];
            proj3x10(vh, tb, smw + K1_WV);
        }

        attn_combine_ln(myx, att, vh, qb, smw);
    }
    pff30_smem(myx, smw);

    {
        float qb[30];
#pragma unroll
        for (int d = 0; d < 30; d++) qb[d] = myx[d];
        float qm[30];
        proj3x10(qm, qb, smw + K1_WQMT);
        float att[9];
        attn_scores_raw(att, qm, qb);
        float vh[30];
        proj3x10(vh, qb, smw + K1_WV);
        attn_combine_ln(myx, att, vh, qb, smw);
    }
    pff30_smem(myx, smw);

#pragma unroll 1
    for (int d = 0; d < 30; d++)
        xout[(size_t)(b * 30 + d) * nr + row] = myx[d];
}

// ===========================================================================
// Kernel 2: PFF(90) + classifier + softmax.
// R14 shape (256 threads, 4 rows/thread, 128-row tile) + j-packed FFMA2:
// weights load as packed u64 pairs (contiguous in j), x splatted per row.
// Per i-step: 24 FMA2 + 4 LDS.128 + 4 movs (vs 48 FFMA + 4 LDS).
// ===========================================================================
#define S3_W1   0        // W1p^T: [i*96 + j], 8640 (pads zero)
#define S3_W2   8640     // W2p^T: [i*96 + j], 8640
#define S3_WC1  17280    // Wc1^T: [i*48 + j], 4320
#define S3_B1P  21600    // 96
#define S3_B2P  21696    // 96
#define S3_G1   21792    // 96
#define S3_BB1  21888    // 96
#define S3_BC1  21984    // 48
#define S3_WC2  22032    // [c*48 + j], 144
#define S3_BC2  22176    // 4
#define S3_X    22180    // x tile: [96][stride 132] = 12672
#define S3_H    34852    // h tile: [96][stride 132] = 12672
#define S3_TOT  47524    // floats = 190096 bytes

#define S3_RS   132
#define NT3     256

__global__ __launch_bounds__(NT3)
void k_phase3(const float* __restrict__ xin,
              const float* __restrict__ W1p, const float* __restrict__ b1p,
              const float* __restrict__ W2p, const float* __restrict__ b2p,
              const float* __restrict__ g1,  const float* __restrict__ bb1,
              const float* __restrict__ Wc1, const float* __restrict__ bc1,
              const float* __restrict__ Wc2, const float* __restrict__ bc2,
              float* __restrict__ out, int nr)
{
    extern __shared__ float sm[];
    const int t = threadIdx.x;

    for (int i = t; i < S3_X; i += NT3) sm[i] = 0.f;
    __syncthreads();
    for (int idx = t; idx < 8100; idx += NT3) {
        int j = idx / 90, i = idx % 90;
        sm[S3_W1 + i*96 + j] = W1p[idx];
        sm[S3_W2 + i*96 + j] = W2p[idx];
    }
    for (int idx = t; idx < 4050; idx += NT3) {
        int j = idx / 90, i = idx % 90;
        sm[S3_WC1 + i*48 + j] = Wc1[idx];
    }
    for (int i = t; i < 90; i += NT3) {
        sm[S3_B1P+i] = b1p[i]; sm[S3_B2P+i] = b2p[i];
        sm[S3_G1+i]  = g1[i];  sm[S3_BB1+i] = bb1[i];
    }
    for (int i = t; i < 45;  i += NT3) sm[S3_BC1 + i] = bc1[i];
    for (int i = t; i < 135; i += NT3) { int c = i / 45, j = i % 45; sm[S3_WC2 + c*48 + j] = Wc2[i]; }
    for (int i = t; i < 3;   i += NT3) sm[S3_BC2 + i] = bc2[i];

    const int row0 = blockIdx.x * 128;

    for (int idx = t; idx < 96 * 128; idx += NT3) {
        int j = idx >> 7, rr = idx & 127;
        float v = 0.f;
        if (j < 90) {
            int gr = row0 + rr;
            if (gr < nr) v = xin[(size_t)j * nr + gr];
        }
        sm[S3_X + j * S3_RS + rr] = v;
    }
    __syncthreads();

    const int lane = t & 31, w = t >> 5;
    const int g = lane >> 2;          // j-group 0..7
    const int c = lane & 3;           // row cluster 0..3
    const int rbase = w * 16 + c * 4; // this thread's 4 tile-rows
    const float* __restrict__ xt = sm + S3_X;
    float*       __restrict__ ht = sm + S3_H;

    u64 acc2[24];   // acc2[q2*4 + rho]: lanes = (j = g*12+2*q2, j+1)

    // ---- GEMV1: h = relu(W1p x + b1p) ----
#pragma unroll
    for (int q2 = 0; q2 < 6; q2++) {
        float2 bb = *reinterpret_cast<const float2*>(sm + S3_B1P + g*12 + q2*2);
        u64 bp = pk2(bb.x, bb.y);
        acc2[q2*4+0] = bp; acc2[q2*4+1] = bp; acc2[q2*4+2] = bp; acc2[q2*4+3] = bp;
    }
    {
        const float* wbase = sm + S3_W1 + g * 12;
#pragma unroll 3
        for (int i = 0; i < 90; i++) {
            float4 xv = *reinterpret_cast<const float4*>(xt + i * S3_RS + rbase);
            u64 x0 = pk2(xv.x, xv.x), x1 = pk2(xv.y, xv.y);
            u64 x2 = pk2(xv.z, xv.z), x3 = pk2(xv.w, xv.w);
            const ulonglong2* wv = reinterpret_cast<const ulonglong2*>(wbase + i * 96);
            ulonglong2 wa = wv[0], wb = wv[1], wc = wv[2];
            u64 wp[6] = { wa.x, wa.y, wb.x, wb.y, wc.x, wc.y };
#pragma unroll
            for (int q2 = 0; q2 < 6; q2++) {
                FMA2(acc2[q2*4+0], wp[q2], x0, acc2[q2*4+0]);
                FMA2(acc2[q2*4+1], wp[q2], x1, acc2[q2*4+1]);
                FMA2(acc2[q2*4+2], wp[q2], x2, acc2[q2*4+2]);
                FMA2(acc2[q2*4+3], wp[q2], x3, acc2[q2*4+3]);
            }
        }
    }
    // unpack + relu + store h (two j rows per q2)
#pragma unroll
    for (int q2 = 0; q2 < 6; q2++) {
        float l0,h0, l1,h1, l2,h2, l3,h3;
        upk2(l0,h0, acc2[q2*4+0]); upk2(l1,h1, acc2[q2*4+1]);
        upk2(l2,h2, acc2[q2*4+2]); upk2(l3,h3, acc2[q2*4+3]);
        int j0 = g*12 + 2*q2;
        float4 he, ho;
        he.x = fmaxf(l0,0.f); he.y = fmaxf(l1,0.f); he.z = fmaxf(l2,0.f); he.w = fmaxf(l3,0.f);
        ho.x = fmaxf(h0,0.f); ho.y = fmaxf(h1,0.f); ho.z = fmaxf(h2,0.f); ho.w = fmaxf(h3,0.f);
        *reinterpret_cast<float4*>(ht + j0      * S3_RS + rbase) = he;
        *reinterpret_cast<float4*>(ht + (j0+1) * S3_RS + rbase) = ho;
    }
    __syncwarp();   // warp w owns rows w*16..w*16+15 entirely

    // ---- GEMV2: x2 = x + W2p h + b2p ----
#pragma unroll
    for (int q2 = 0; q2 < 6; q2++) {
        float2 bb = *reinterpret_cast<const float2*>(sm + S3_B2P + g*12 + q2*2);
        u64 bp = pk2(bb.x, bb.y);
        acc2[q2*4+0] = bp; acc2[q2*4+1] = bp; acc2[q2*4+2] = bp; acc2[q2*4+3] = bp;
    }
    {
        const float* wbase = sm + S3_W2 + g * 12;
#pragma unroll 3
        for (int i = 0; i < 90; i++) {
            float4 hv = *reinterpret_cast<const float4*>(ht + i * S3_RS + rbase);
            u64 x0 = pk2(hv.x, hv.x), x1 = pk2(hv.y, hv.y);
            u64 x2 = pk2(hv.z, hv.z), x3 = pk2(hv.w, hv.w);
            const ulonglong2* wv = reinterpret_cast<const ulonglong2*>(wbase + i * 96);
            ulonglong2 wa = wv[0], wb = wv[1], wc = wv[2];
            u64 wp[6] = { wa.x, wa.y, wb.x, wb.y, wc.x, wc.y };
#pragma unroll
            for (int q2 = 0; q2 < 6; q2++) {
                FMA2(acc2[q2*4+0], wp[q2], x0, acc2[q2*4+0]);
                FMA2(acc2[q2*4+1], wp[q2], x1, acc2[q2*4+1]);
                FMA2(acc2[q2*4+2], wp[q2], x2, acc2[q2*4+2]);
                FMA2(acc2[q2*4+3], wp[q2], x3, acc2[q2*4+3]);
            }
        }
    }
    // unpack to scalar acc[q*4+rho], q = 0..11 <-> j = g*12+q
    float acc[48];
#pragma unroll
    for (int q2 = 0; q2 < 6; q2++) {
#pragma unroll
        for (int rho = 0; rho < 4; rho++) {
            float lo, hi;
            upk2(lo, hi, acc2[q2*4+rho]);
            acc[(2*q2)*4   + rho] = lo;
            acc[(2*q2+1)*4 + rho] = hi;
        }
    }
    float s0 = 0.f, s1 = 0.f, s2 = 0.f, s3 = 0.f;
#pragma unroll
    for (int q = 0; q < 12; q++) {
        int j = g*12 + q;
        float4 xv = *reinterpret_cast<const float4*>(xt + j * S3_RS + rbase);
        acc[q*4+0] += xv.x; acc[q*4+1] += xv.y; acc[q*4+2] += xv.z; acc[q*4+3] += xv.w;
        s0 += acc[q*4+0]; s1 += acc[q*4+1]; s2 += acc[q*4+2]; s3 += acc[q*4+3];
    }
#pragma unroll
    for (int m = 4; m < 32; m <<= 1) {
        s0 += __shfl_xor_sync(0xffffffffu, s0, m);
        s1 += __shfl_xor_sync(0xffffffffu, s1, m);
        s2 += __shfl_xor_sync(0xffffffffu, s2, m);
        s3 += __shfl_xor_sync(0xffffffffu, s3, m);
    }
    float m0 = s0 * (1.f/90.f), m1 = s1 * (1.f/90.f);
    float m2 = s2 * (1.f/90.f), m3 = s3 * (1.f/90.f);
    float v0 = 0.f, v1 = 0.f, v2 = 0.f, v3 = 0.f;
#pragma unroll
    for (int q = 0; q < 12; q++) {
        int j = g*12 + q;
        if (j < 90) {
            float d0 = acc[q*4+0]-m0, d1 = acc[q*4+1]-m1;
            float d2 = acc[q*4+2]-m2, d3 = acc[q*4+3]-m3;
            v0 = fmaf(d0,d0,v0); v1 = fmaf(d1,d1,v1);
            v2 = fmaf(d2,d2,v2); v3 = fmaf(d3,d3,v3);
        }
    }
#pragma unroll
    for (int m = 4; m < 32; m <<= 1) {
        v0 += __shfl_xor_sync(0xffffffffu, v0, m);
        v1 += __shfl_xor_sync(0xffffffffu, v1, m);
        v2 += __shfl_xor_sync(0xffffffffu, v2, m);
        v3 += __shfl_xor_sync(0xffffffffu, v3, m);
    }
    float r0 = rsqrtf(fmaf(v0, 1.f/90.f, LN_EPS));
    float r1 = rsqrtf(fmaf(v1, 1.f/90.f, LN_EPS));
    float r2 = rsqrtf(fmaf(v2, 1.f/90.f, LN_EPS));
    float r3 = rsqrtf(fmaf(v3, 1.f/90.f, LN_EPS));

    __syncwarp();
#pragma unroll
    for (int q = 0; q < 12; q++) {
        int j = g*12 + q;
        float4 xn;
        if (j < 90) {
            float gg = sm[S3_G1 + j], bb = sm[S3_BB1 + j];
            xn.x = fmaf((acc[q*4+0]-m0)*r0, gg, bb);
            xn.y = fmaf((acc[q*4+1]-m1)*r1, gg, bb);
            xn.z = fmaf((acc[q*4+2]-m2)*r2, gg, bb);
            xn.w = fmaf((acc[q*4+3]-m3)*r3, gg, bb);
        } else {
            xn.x = xn.y = xn.z = xn.w = 0.f;
        }
        *reinterpret_cast<float4*>(ht + j * S3_RS + rbase) = xn;
    }
    __syncwarp();

    // ---- classifier: j-packed FMA2, lane owns j = g*6..g*6+5, 4 rows ----
    u64 cacc2[12];   // cacc2[q2*4 + rho]: lanes = (j = g*6+2*q2, j+1)
#pragma unroll
    for (int q2 = 0; q2 < 3; q2++) {
        float2 bb = *reinterpret_cast<const float2*>(sm + S3_BC1 + g*6 + q2*2);
        u64 bp = pk2(bb.x, bb.y);
        cacc2[q2*4+0] = bp; cacc2[q2*4+1] = bp; cacc2[q2*4+2] = bp; cacc2[q2*4+3] = bp;
    }
    {
        const float* wbase = sm + S3_WC1 + g * 6;
#pragma unroll 3
        for (int i = 0; i < 90; i++) {
            float4 xv = *reinterpret_cast<const float4*>(ht + i * S3_RS + rbase);
            u64 x0 = pk2(xv.x, xv.x), x1 = pk2(xv.y, xv.y);
            u64 x2 = pk2(xv.z, xv.z), x3 = pk2(xv.w, xv.w);
            const u64* wp = reinterpret_cast<const u64*>(wbase + i * 48);
            u64 w0 = wp[0], w1 = wp[1], w2 = wp[2];
            FMA2(cacc2[0*4+0], w0, x0, cacc2[0*4+0]);
            FMA2(cacc2[0*4+1], w0, x1, cacc2[0*4+1]);
            FMA2(cacc2[0*4+2], w0, x2, cacc2[0*4+2]);
            FMA2(cacc2[0*4+3], w0, x3, cacc2[0*4+3]);
            FMA2(cacc2[1*4+0], w1, x0, cacc2[1*4+0]);
            FMA2(cacc2[1*4+1], w1, x1, cacc2[1*4+1]);
            FMA2(cacc2[1*4+2], w1, x2, cacc2[1*4+2]);
            FMA2(cacc2[1*4+3], w1, x3, cacc2[1*4+3]);
            FMA2(cacc2[2*4+0], w2, x0, cacc2[2*4+0]);
            FMA2(cacc2[2*4+1], w2, x1, cacc2[2*4+1]);
            FMA2(cacc2[2*4+2], w2, x2, cacc2[2*4+2]);
            FMA2(cacc2[2*4+3], w2, x3, cacc2[2*4+3]);
        }
    }
    float cacc[24];  // cacc[q*4+rho], q = 0..5 <-> j = g*6+q
#pragma unroll
    for (int q2 = 0; q2 < 3; q2++) {
#pragma unroll
        for (int rho = 0; rho < 4; rho++) {
            float lo, hi;
            upk2(lo, hi, cacc2[q2*4+rho]);
            cacc[(2*q2)*4   + rho] = lo;
            cacc[(2*q2+1)*4 + rho] = hi;
        }
    }
    float lg[12];    // lg[cc*4 + rho]
#pragma unroll
    for (int i = 0; i < 12; i++) lg[i] = 0.f;
#pragma unroll
    for (int q = 0; q < 6; q++) {
        int j = g*6 + q;
        float w0 = sm[S3_WC2 + j];
        float w1 = sm[S3_WC2 + 48 + j];
        float w2 = sm[S3_WC2 + 96 + j];
#pragma unroll
        for (int rho = 0; rho < 4; rho++) {
            float a = fmaxf(cacc[q*4+rho], 0.f);
            lg[0*4+rho] = fmaf(a, w0, lg[0*4+rho]);
            lg[1*4+rho] = fmaf(a, w1, lg[1*4+rho]);
            lg[2*4+rho] = fmaf(a, w2, lg[2*4+rho]);
        }
    }
#pragma unroll
    for (int m = 4; m < 32; m <<= 1)
#pragma unroll
        for (int i = 0; i < 12; i++)
            lg[i] += __shfl_xor_sync(0xffffffffu, lg[i], m);
    float bc20 = sm[S3_BC2+0], bc21 = sm[S3_BC2+1], bc22 = sm[S3_BC2+2];
#pragma unroll
    for (int rho = 0; rho < 4; rho++) {
        float l0 = lg[rho] + bc20, l1 = lg[4+rho] + bc21, l2 = lg[8+rho] + bc22;
        float mm = fmaxf(l0, fmaxf(l1, l2));
        float e0 = __expf(l0 - mm), e1 = __expf(l1 - mm), e2 = __expf(l2 - mm);
        float inv = __frcp_rn(e0 + e1 + e2);
        int row = row0 + rbase + rho;
        if (row < nr && g < 3) {
            float e = (g == 0) ? e0 : (g == 1) ? e1 : e2;
            out[(size_t)row * 3 + g] = e * inv;
        }
    }
}

// ===========================================================================
extern "C" void kernel_launch(void* const* d_in, const int* in_sizes, int n_in,
                              void* d_out, int out_size)
{
    const float* A[24];
    for (int i = 0; i < 24; i++) A[i] = (const float*)d_in[i];

    int nr = in_sizes[0] / 90;
    if (nr > NRMAX) nr = NRMAX;

    float *qt, *kt, *vt, *mid, *MT;
    cudaGetSymbolAddress((void**)&qt,  g_qt);
    cudaGetSymbolAddress((void**)&kt,  g_kt);
    cudaGetSymbolAddress((void**)&vt,  g_vt);
    cudaGetSymbolAddress((void**)&mid, g_mid);
    cudaGetSymbolAddress((void**)&MT,  g_MT);

    k_precompute<<<1, 128>>>(A[3], A[4], MT);

    int btr = (nr + 31) / 32;
    dim3 g0(btr, 3);
    k_transpose3<<<g0, 256>>>(A[0], A[1], A[2], qt, kt, vt, nr);

    int bx = (nr + 255) / 256;
    dim3 g1(bx, 3);
    k_phase12<<<g1, 256>>>(qt, kt, vt,
                           MT, A[5],
                           A[6], A[7],
                           A[8], A[9], A[10], A[11],
                           A[12], A[13],
                           mid, nr);

    int bx3 = (nr + 127) / 128;
    cudaFuncSetAttribute(k_phase3, cudaFuncAttributeMaxDynamicSharedMemorySize,
                         S3_TOT * (int)sizeof(float));
    k_phase3<<<bx3, NT3, S3_TOT * sizeof(float)>>>(
        mid,
        A[14], A[15], A[16], A[17],
        A[18], A[19],
        A[20], A[21], A[22], A[23],
        (float*)d_out, nr);
}

// round 17
// speedup vs baseline: 1.5339x; 1.0662x over previous
#include <cuda_runtime.h>

#define LN_EPS   1e-6f
#define INV_TEMP 0.31622776601683794f   // 1/sqrt(10)
#define NRMAX    131072

typedef unsigned long long u64;

// Packed f32x2 helpers (sm_103a)
__device__ __forceinline__ u64 pk2(float lo, float hi) {
    u64 r; asm("mov.b64 %0, {%1, %2};" : "=l"(r) : "f"(lo), "f"(hi)); return r;
}
__device__ __forceinline__ void upk2(float& lo, float& hi, u64 v) {
    asm("mov.b64 {%0, %1}, %2;" : "=f"(lo), "=f"(hi) : "l"(v));
}
#define FMA2(d, a, b, c) \
    asm("fma.rn.f32x2 %0, %1, %2, %3;" : "=l"(d) : "l"(a), "l"(b), "l"(c))

// Sanctioned __device__ scratch.
__device__ float g_qt[(size_t)90 * NRMAX];
__device__ float g_kt[(size_t)90 * NRMAX];
__device__ float g_vt[(size_t)90 * NRMAX];
__device__ float g_mid[(size_t)90 * NRMAX];
__device__ float g_MT[100];

// ===========================================================================
// Kernel P: precompute MT = Wq^T Wk / sqrt(10).
// ===========================================================================
__global__ void k_precompute(const float* __restrict__ Wq,
                             const float* __restrict__ Wk,
                             float* __restrict__ MT)
{
    int t = threadIdx.x;
    if (t < 100) {
        int j = t / 10, i = t % 10;
        float s = 0.f;
#pragma unroll
        for (int o = 0; o < 10; o++) s = fmaf(Wq[o*10+i], Wk[o*10+j], s);
        MT[j*10 + i] = s * INV_TEMP;
    }
}

// ===========================================================================
// Kernel 0: tiled transpose [B,90] -> [90,B]; div-free indexing.
// ===========================================================================
__global__ __launch_bounds__(256)
void k_transpose3(const float* __restrict__ q_in, const float* __restrict__ k_in,
                  const float* __restrict__ v_in,
                  float* __restrict__ q_out, float* __restrict__ k_out,
                  float* __restrict__ v_out, int nr)
{
    const float* in   = (blockIdx.y == 0) ? q_in  : (blockIdx.y == 1) ? k_in  : v_in;
    float*       outp = (blockIdx.y == 0) ? q_out : (blockIdx.y == 1) ? k_out : v_out;

    __shared__ float ts[90 * 33];
    const int t = threadIdx.x;
    const int lane = t & 31, w = t >> 5;       // 8 warps x 4 rows each
    const int row0 = blockIdx.x * 32;
    const size_t base = (size_t)row0 * 90;

#pragma unroll
    for (int rr = 0; rr < 4; rr++) {
        int r = w * 4 + rr;
        bool ok = (row0 + r) < nr;
        const float* rp = in + base + r * 90;
#pragma unroll
        for (int k = 0; k < 3; k++) {
            int c = lane + k * 32;
            if (c < 90) ts[c * 33 + r] = ok ? rp[c] : 0.f;
        }
    }
    __syncthreads();
    for (int idx = t; idx < 2880; idx += 256) {
        int c = idx >> 5, r = idx & 31;
        if (row0 + r < nr)
            outp[(size_t)c * nr + row0 + r] = ts[c * 33 + r];
    }
}

// ===========================================================================
// Kernel 1: phases 1+2. One thread per (row, branch).
// ===========================================================================
#define K1_WQMT 0
#define K1_WV   100
#define K1_GM   200
#define K1_BM   212
#define K1_B1   224
#define K1_B2   256
#define K1_GP   288
#define K1_BP   320
#define K1_W1T  352
#define K1_W2R  1312
#define K1_TOT  2272
#define SX_STRIDE 33

__device__ __forceinline__ void proj3x10(float o[30], const float in[30],
                                         const float* __restrict__ W)
{
#pragma unroll
    for (int oo = 0; oo < 10; oo++) {
        const float2* wp = reinterpret_cast<const float2*>(W + oo * 10);
        float w[10];
#pragma unroll
        for (int p = 0; p < 5; p++) { float2 u = wp[p]; w[2*p] = u.x; w[2*p+1] = u.y; }
#pragma unroll
        for (int s = 0; s < 3; s++) {
            float a0 = 0.f, a1 = 0.f;
#pragma unroll
            for (int i = 0; i < 5; i++) {
                a0 = fmaf(in[s*10+i],   w[i],   a0);
                a1 = fmaf(in[s*10+5+i], w[5+i], a1);
            }
            o[s*10+oo] = a0 + a1;
        }
    }
}

__device__ __forceinline__ void attn_scores_raw(float att[9], const float qm[30],
                                                const float kb[30])
{
#pragma unroll
    for (int s = 0; s < 3; s++)
#pragma unroll
        for (int tt = 0; tt < 3; tt++) {
            float a0 = 0.f, a1 = 0.f;
#pragma unroll
            for (int d = 0; d < 5; d++) {
                a0 = fmaf(qm[s*10+d],   kb[tt*10+d],   a0);
                a1 = fmaf(qm[s*10+5+d], kb[tt*10+5+d], a1);
            }
            att[s*3+tt] = a0 + a1;
        }
}

__device__ __forceinline__ void attn_combine_ln(float* __restrict__ xs,
                                                const float att[9],
                                                const float vh[30],
                                                const float qb[30],
                                                const float* __restrict__ smw)
{
#pragma unroll
    for (int s = 0; s < 3; s++) {
        float t10[10];
        float m = 0.f;
#pragma unroll
        for (int d = 0; d < 10; d++) {
            float a = qb[s*10+d];
            a = fmaf(att[s*3+0], vh[d],    a);
            a = fmaf(att[s*3+1], vh[10+d], a);
            a = fmaf(att[s*3+2], vh[20+d], a);
            t10[d] = a; m += a;
        }
        m *= 0.1f;
        float vv0 = 0.f, vv1 = 0.f;
#pragma unroll
        for (int d = 0; d < 5; d++) {
            float d0 = t10[d] - m, d1 = t10[5+d] - m;
            vv0 = fmaf(d0, d0, vv0);
            vv1 = fmaf(d1, d1, vv1);
        }
        float r = rsqrtf(fmaf(vv0 + vv1, 0.1f, LN_EPS));
#pragma unroll
        for (int d = 0; d < 10; d++)
            xs[s*10+d] = fmaf((t10[d] - m) * r, smw[K1_GM+d], smw[K1_BM+d]);
    }
}

__device__ __forceinline__ void pff30_smem(float* __restrict__ xs,
                                           const float* __restrict__ smw)
{
    u64 h2[16];
    {
        const float2* b1p = reinterpret_cast<const float2*>(smw + K1_B1);
#pragma unroll
        for (int j2 = 0; j2 < 15; j2++) { float2 b = b1p[j2]; h2[j2] = pk2(b.x, b.y); }
        h2[15] = 0ull;
    }
    // GEMV1 with explicit x prefetch (xs[30] is in-slice pad, unused)
    float xnext = xs[0];
#pragma unroll 1
    for (int i = 0; i < 30; i++) {
        u64 xi2 = pk2(xnext, xnext);
        xnext = xs[i + 1];
        const ulonglong2* wr = reinterpret_cast<const ulonglong2*>(smw + K1_W1T + i*32);
#pragma unroll
        for (int j8 = 0; j8 < 8; j8++) {
            ulonglong2 ww = wr[j8];
            FMA2(h2[2*j8],   xi2, ww.x, h2[2*j8]);
            FMA2(h2[2*j8+1], xi2, ww.y, h2[2*j8+1]);
        }
    }
#pragma unroll
    for (int j2 = 0; j2 < 16; j2++) {
        float lo, hi; upk2(lo, hi, h2[j2]);
        h2[j2] = pk2(fmaxf(lo, 0.f), fmaxf(hi, 0.f));
    }
    float mean = 0.f;
#pragma unroll 1
    for (int j = 0; j < 30; j++) {
        u64 p0 = pk2(smw[K1_B2+j], 0.f), p1 = 0ull, p2 = 0ull, p3 = 0ull;
        const ulonglong2* wr = reinterpret_cast<const ulonglong2*>(smw + K1_W2R + j*32);
#pragma unroll
        for (int i8 = 0; i8 < 4; i8++) {
            ulonglong2 wa = wr[2*i8], wb = wr[2*i8+1];
            FMA2(p0, h2[4*i8+0], wa.x, p0);
            FMA2(p1, h2[4*i8+1], wa.y, p1);
            FMA2(p2, h2[4*i8+2], wb.x, p2);
            FMA2(p3, h2[4*i8+3], wb.y, p3);
        }
        float l0, u0, l1, u1, l2, u2, l3, u3;
        upk2(l0, u0, p0); upk2(l1, u1, p1); upk2(l2, u2, p2); upk2(l3, u3, p3);
        float a = ((l0 + u0) + (l1 + u1)) + ((l2 + u2) + (l3 + u3)) + xs[j];
        xs[j] = a;
        mean += a;
    }
    mean *= (1.f / 30.f);
    float v0 = 0.f, v1 = 0.f;
#pragma unroll 1
    for (int j = 0; j < 30; j += 2) {
        float d0 = xs[j] - mean, d1 = xs[j+1] - mean;
        v0 = fmaf(d0, d0, v0);
        v1 = fmaf(d1, d1, v1);
    }
    float r = rsqrtf(fmaf(v0 + v1, 1.f / 30.f, LN_EPS));
#pragma unroll 1
    for (int j = 0; j < 30; j++)
        xs[j] = fmaf((xs[j] - mean) * r, smw[K1_GP+j], smw[K1_BP+j]);
}

__global__ __launch_bounds__(256, 2)
void k_phase12(const float* __restrict__ gq, const float* __restrict__ gk,
               const float* __restrict__ gv,
               const float* __restrict__ MT, const float* __restrict__ Wv,
               const float* __restrict__ gm, const float* __restrict__ bm,
               const float* __restrict__ W1, const float* __restrict__ b1,
               const float* __restrict__ W2, const float* __restrict__ b2,
               const float* __restrict__ gp, const float* __restrict__ bp,
               float* __restrict__ xout, int nr)
{
    __shared__ float smw[K1_TOT];
    __shared__ float sx[256 * SX_STRIDE];
    {
        int t = threadIdx.x;
        for (int i = t; i < 100; i += 256) { smw[K1_WQMT+i] = MT[i]; smw[K1_WV+i] = Wv[i]; }
        if (t < 10) { smw[K1_GM+t] = gm[t]; smw[K1_BM+t] = bm[t]; }
        if (t >= 32 && t < 62) {
            int j = t - 32;
            smw[K1_B1+j] = b1[j]; smw[K1_B2+j] = b2[j]; smw[K1_GP+j] = gp[j]; smw[K1_BP+j] = bp[j];
        }
        for (int i = t; i < 1920; i += 256) smw[K1_W1T + i] = 0.f;
        __syncthreads();
        for (int idx = t; idx < 900; idx += 256) {
            int j = idx / 30, i = idx % 30;
            smw[K1_W1T + i*32 + j] = W1[idx];
            smw[K1_W2R + j*32 + i] = W2[idx];
        }
    }
    __syncthreads();

    const int row = blockIdx.x * 256 + threadIdx.x;
    const int b   = blockIdx.y;
    if (row >= nr) return;

    float* __restrict__ myx = sx + threadIdx.x * SX_STRIDE;

    {
        const float* qc = gq + (size_t)b * 30 * nr + row;
        float qb[30];
#pragma unroll
        for (int d = 0; d < 30; d++) qb[d] = qc[(size_t)d * nr];

        float qm[30];
        proj3x10(qm, qb, smw + K1_WQMT);

        float att[9];
        {
            const float* kc = gk + (size_t)b * 30 * nr + row;
            float kb[30];
#pragma unroll
            for (int d = 0; d < 30; d++) kb[d] = kc[(size_t)d * nr];
            attn_scores_raw(att, qm, kb);
        }

        float vh[30];
        {
            const float* vc = gv + (size_t)b * 30 * nr + row;
            float tb[30];
#pragma unroll
            for (int d = 0; d < 30; d++) tb[d] = vc[(size_t)d * nr];
            proj3x10(vh, tb, smw + K1_WV);
        }

        attn_combine_ln(myx, att, vh, qb, smw);
    }
    pff30_smem(myx, smw);

    {
        float qb[30];
#pragma unroll
        for (int d = 0; d < 30; d++) qb[d] = myx[d];
        float qm[30];
        proj3x10(qm, qb, smw + K1_WQMT);
        float att[9];
        attn_scores_raw(att, qm, qb);
        float vh[30];
        proj3x10(vh, qb, smw + K1_WV);
        attn_combine_ln(myx, att, vh, qb, smw);
    }
    pff30_smem(myx, smw);

#pragma unroll 1
    for (int d = 0; d < 30; d++)
        xout[(size_t)(b * 30 + d) * nr + row] = myx[d];
}

// ===========================================================================
// Kernel 2: PFF(90) + classifier + softmax. 4 rows/thread, j-packed FFMA2,
// explicit next-i prefetch of x and weight vectors in all GEMV loops.
// ===========================================================================
#define S3_W1   0        // W1p^T: [i*96 + j], 8640 (pads zero)
#define S3_W2   8640     // W2p^T: [i*96 + j], 8640
#define S3_WC1  17280    // Wc1^T: [i*48 + j], 4320
#define S3_B1P  21600    // 96
#define S3_B2P  21696    // 96
#define S3_G1   21792    // 96
#define S3_BB1  21888    // 96
#define S3_BC1  21984    // 48
#define S3_WC2  22032    // [c*48 + j], 144
#define S3_BC2  22176    // 4
#define S3_X    22180    // x tile: [96][stride 132] = 12672
#define S3_H    34852    // h tile: [96][stride 132] = 12672
#define S3_TOT  47524    // floats = 190096 bytes

#define S3_RS   132
#define NT3     256

__global__ __launch_bounds__(NT3)
void k_phase3(const float* __restrict__ xin,
              const float* __restrict__ W1p, const float* __restrict__ b1p,
              const float* __restrict__ W2p, const float* __restrict__ b2p,
              const float* __restrict__ g1,  const float* __restrict__ bb1,
              const float* __restrict__ Wc1, const float* __restrict__ bc1,
              const float* __restrict__ Wc2, const float* __restrict__ bc2,
              float* __restrict__ out, int nr)
{
    extern __shared__ float sm[];
    const int t = threadIdx.x;

    for (int i = t; i < S3_X; i += NT3) sm[i] = 0.f;
    __syncthreads();
    for (int idx = t; idx < 8100; idx += NT3) {
        int j = idx / 90, i = idx % 90;
        sm[S3_W1 + i*96 + j] = W1p[idx];
        sm[S3_W2 + i*96 + j] = W2p[idx];
    }
    for (int idx = t; idx < 4050; idx += NT3) {
        int j = idx / 90, i = idx % 90;
        sm[S3_WC1 + i*48 + j] = Wc1[idx];
    }
    for (int i = t; i < 90; i += NT3) {
        sm[S3_B1P+i] = b1p[i]; sm[S3_B2P+i] = b2p[i];
        sm[S3_G1+i]  = g1[i];  sm[S3_BB1+i] = bb1[i];
    }
    for (int i = t; i < 45;  i += NT3) sm[S3_BC1 + i] = bc1[i];
    for (int i = t; i < 135; i += NT3) { int c = i / 45, j = i % 45; sm[S3_WC2 + c*48 + j] = Wc2[i]; }
    for (int i = t; i < 3;   i += NT3) sm[S3_BC2 + i] = bc2[i];

    const int row0 = blockIdx.x * 128;

    for (int idx = t; idx < 96 * 128; idx += NT3) {
        int j = idx >> 7, rr = idx & 127;
        float v = 0.f;
        if (j < 90) {
            int gr = row0 + rr;
            if (gr < nr) v = xin[(size_t)j * nr + gr];
        }
        sm[S3_X + j * S3_RS + rr] = v;
    }
    __syncthreads();

    const int lane = t & 31, w = t >> 5;
    const int g = lane >> 2;          // j-group 0..7
    const int c = lane & 3;           // row cluster 0..3
    const int rbase = w * 16 + c * 4; // this thread's 4 tile-rows
    const float* __restrict__ xt = sm + S3_X;
    float*       __restrict__ ht = sm + S3_H;

    u64 acc2[24];

    // ---- GEMV1: h = relu(W1p x + b1p), prefetched ----
#pragma unroll
    for (int q2 = 0; q2 < 6; q2++) {
        float2 bb = *reinterpret_cast<const float2*>(sm + S3_B1P + g*12 + q2*2);
        u64 bp = pk2(bb.x, bb.y);
        acc2[q2*4+0] = bp; acc2[q2*4+1] = bp; acc2[q2*4+2] = bp; acc2[q2*4+3] = bp;
    }
    {
        const float* wbase = sm + S3_W1 + g * 12;
        float4 xv = *reinterpret_cast<const float4*>(xt + rbase);
        const ulonglong2* wv0 = reinterpret_cast<const ulonglong2*>(wbase);
        ulonglong2 wa = wv0[0], wb = wv0[1], wc = wv0[2];
#pragma unroll 3
        for (int i = 0; i < 90; i++) {
            float4 xc = xv;
            ulonglong2 wA = wa, wB = wb, wC = wc;
            // prefetch next (i=89 reads in-bounds pad rows; values unused)
            xv = *reinterpret_cast<const float4*>(xt + (i+1) * S3_RS + rbase);
            const ulonglong2* wn = reinterpret_cast<const ulonglong2*>(wbase + (i+1) * 96);
            wa = wn[0]; wb = wn[1]; wc = wn[2];
            u64 x0 = pk2(xc.x, xc.x), x1 = pk2(xc.y, xc.y);
            u64 x2 = pk2(xc.z, xc.z), x3 = pk2(xc.w, xc.w);
            u64 wp[6] = { wA.x, wA.y, wB.x, wB.y, wC.x, wC.y };
#pragma unroll
            for (int q2 = 0; q2 < 6; q2++) {
                FMA2(acc2[q2*4+0], wp[q2], x0, acc2[q2*4+0]);
                FMA2(acc2[q2*4+1], wp[q2], x1, acc2[q2*4+1]);
                FMA2(acc2[q2*4+2], wp[q2], x2, acc2[q2*4+2]);
                FMA2(acc2[q2*4+3], wp[q2], x3, acc2[q2*4+3]);
            }
        }
    }
#pragma unroll
    for (int q2 = 0; q2 < 6; q2++) {
        float l0,h0, l1,h1, l2,h2, l3,h3;
        upk2(l0,h0, acc2[q2*4+0]); upk2(l1,h1, acc2[q2*4+1]);
        upk2(l2,h2, acc2[q2*4+2]); upk2(l3,h3, acc2[q2*4+3]);
        int j0 = g*12 + 2*q2;
        float4 he, ho;
        he.x = fmaxf(l0,0.f); he.y = fmaxf(l1,0.f); he.z = fmaxf(l2,0.f); he.w = fmaxf(l3,0.f);
        ho.x = fmaxf(h0,0.f); ho.y = fmaxf(h1,0.f); ho.z = fmaxf(h2,0.f); ho.w = fmaxf(h3,0.f);
        *reinterpret_cast<float4*>(ht + j0      * S3_RS + rbase) = he;
        *reinterpret_cast<float4*>(ht + (j0+1) * S3_RS + rbase) = ho;
    }
    __syncwarp();

    // ---- GEMV2: x2 = x + W2p h + b2p, prefetched ----
#pragma unroll
    for (int q2 = 0; q2 < 6; q2++) {
        float2 bb = *reinterpret_cast<const float2*>(sm + S3_B2P + g*12 + q2*2);
        u64 bp = pk2(bb.x, bb.y);
        acc2[q2*4+0] = bp; acc2[q2*4+1] = bp; acc2[q2*4+2] = bp; acc2[q2*4+3] = bp;
    }
    {
        const float* wbase = sm + S3_W2 + g * 12;
        float4 xv = *reinterpret_cast<const float4*>(ht + rbase);
        const ulonglong2* wv0 = reinterpret_cast<const ulonglong2*>(wbase);
        ulonglong2 wa = wv0[0], wb = wv0[1], wc = wv0[2];
#pragma unroll 3
        for (int i = 0; i < 90; i++) {
            float4 xc = xv;
            ulonglong2 wA = wa, wB = wb, wC = wc;
            xv = *reinterpret_cast<const float4*>(ht + (i+1) * S3_RS + rbase);
            const ulonglong2* wn = reinterpret_cast<const ulonglong2*>(wbase + (i+1) * 96);
            wa = wn[0]; wb = wn[1]; wc = wn[2];
            u64 x0 = pk2(xc.x, xc.x), x1 = pk2(xc.y, xc.y);
            u64 x2 = pk2(xc.z, xc.z), x3 = pk2(xc.w, xc.w);
            u64 wp[6] = { wA.x, wA.y, wB.x, wB.y, wC.x, wC.y };
#pragma unroll
            for (int q2 = 0; q2 < 6; q2++) {
                FMA2(acc2[q2*4+0], wp[q2], x0, acc2[q2*4+0]);
                FMA2(acc2[q2*4+1], wp[q2], x1, acc2[q2*4+1]);
                FMA2(acc2[q2*4+2], wp[q2], x2, acc2[q2*4+2]);
                FMA2(acc2[q2*4+3], wp[q2], x3, acc2[q2*4+3]);
            }
        }
    }
    float acc[48];
#pragma unroll
    for (int q2 = 0; q2 < 6; q2++) {
#pragma unroll
        for (int rho = 0; rho < 4; rho++) {
            float lo, hi;
            upk2(lo, hi, acc2[q2*4+rho]);
            acc[(2*q2)*4   + rho] = lo;
            acc[(2*q2+1)*4 + rho] = hi;
        }
    }
    float s0 = 0.f, s1 = 0.f, s2 = 0.f, s3 = 0.f;
#pragma unroll
    for (int q = 0; q < 12; q++) {
        int j = g*12 + q;
        float4 xv = *reinterpret_cast<const float4*>(xt + j * S3_RS + rbase);
        acc[q*4+0] += xv.x; acc[q*4+1] += xv.y; acc[q*4+2] += xv.z; acc[q*4+3] += xv.w;
        s0 += acc[q*4+0]; s1 += acc[q*4+1]; s2 += acc[q*4+2]; s3 += acc[q*4+3];
    }
#pragma unroll
    for (int m = 4; m < 32; m <<= 1) {
        s0 += __shfl_xor_sync(0xffffffffu, s0, m);
        s1 += __shfl_xor_sync(0xffffffffu, s1, m);
        s2 += __shfl_xor_sync(0xffffffffu, s2, m);
        s3 += __shfl_xor_sync(0xffffffffu, s3, m);
    }
    float m0 = s0 * (1.f/90.f), m1 = s1 * (1.f/90.f);
    float m2 = s2 * (1.f/90.f), m3 = s3 * (1.f/90.f);
    float v0 = 0.f, v1 = 0.f, v2 = 0.f, v3 = 0.f;
#pragma unroll
    for (int q = 0; q < 12; q++) {
        int j = g*12 + q;
        if (j < 90) {
            float d0 = acc[q*4+0]-m0, d1 = acc[q*4+1]-m1;
            float d2 = acc[q*4+2]-m2, d3 = acc[q*4+3]-m3;
            v0 = fmaf(d0,d0,v0); v1 = fmaf(d1,d1,v1);
            v2 = fmaf(d2,d2,v2); v3 = fmaf(d3,d3,v3);
        }
    }
#pragma unroll
    for (int m = 4; m < 32; m <<= 1) {
        v0 += __shfl_xor_sync(0xffffffffu, v0, m);
        v1 += __shfl_xor_sync(0xffffffffu, v1, m);
        v2 += __shfl_xor_sync(0xffffffffu, v2, m);
        v3 += __shfl_xor_sync(0xffffffffu, v3, m);
    }
    float r0 = rsqrtf(fmaf(v0, 1.f/90.f, LN_EPS));
    float r1 = rsqrtf(fmaf(v1, 1.f/90.f, LN_EPS));
    float r2 = rsqrtf(fmaf(v2, 1.f/90.f, LN_EPS));
    float r3 = rsqrtf(fmaf(v3, 1.f/90.f, LN_EPS));

    __syncwarp();
#pragma unroll
    for (int q = 0; q < 12; q++) {
        int j = g*12 + q;
        float4 xn;
        if (j < 90) {
            float gg = sm[S3_G1 + j], bb = sm[S3_BB1 + j];
            xn.x = fmaf((acc[q*4+0]-m0)*r0, gg, bb);
            xn.y = fmaf((acc[q*4+1]-m1)*r1, gg, bb);
            xn.z = fmaf((acc[q*4+2]-m2)*r2, gg, bb);
            xn.w = fmaf((acc[q*4+3]-m3)*r3, gg, bb);
        } else {
            xn.x = xn.y = xn.z = xn.w = 0.f;
        }
        *reinterpret_cast<float4*>(ht + j * S3_RS + rbase) = xn;
    }
    __syncwarp();

    // ---- classifier: j-packed FMA2, prefetched ----
    u64 cacc2[12];
#pragma unroll
    for (int q2 = 0; q2 < 3; q2++) {
        float2 bb = *reinterpret_cast<const float2*>(sm + S3_BC1 + g*6 + q2*2);
        u64 bp = pk2(bb.x, bb.y);
        cacc2[q2*4+0] = bp; cacc2[q2*4+1] = bp; cacc2[q2*4+2] = bp; cacc2[q2*4+3] = bp;
    }
    {
        const float* wbase = sm + S3_WC1 + g * 6;
        float4 xv = *reinterpret_cast<const float4*>(ht + rbase);
        const u64* wv0 = reinterpret_cast<const u64*>(wbase);
        u64 w0 = wv0[0], w1 = wv0[1], w2 = wv0[2];
#pragma unroll 3
        for (int i = 0; i < 90; i++) {
            float4 xc = xv;
            u64 wA = w0, wB = w1, wC = w2;
            xv = *reinterpret_cast<const float4*>(ht + (i+1) * S3_RS + rbase);
            const u64* wn = reinterpret_cast<const u64*>(wbase + (i+1) * 48);
            w0 = wn[0]; w1 = wn[1]; w2 = wn[2];
            u64 x0 = pk2(xc.x, xc.x), x1 = pk2(xc.y, xc.y);
            u64 x2 = pk2(xc.z, xc.z), x3 = pk2(xc.w, xc.w);
            FMA2(cacc2[0*4+0], wA, x0, cacc2[0*4+0]);
            FMA2(cacc2[0*4+1], wA, x1, cacc2[0*4+1]);
            FMA2(cacc2[0*4+2], wA, x2, cacc2[0*4+2]);
            FMA2(cacc2[0*4+3], wA, x3, cacc2[0*4+3]);
            FMA2(cacc2[1*4+0], wB, x0, cacc2[1*4+0]);
            FMA2(cacc2[1*4+1], wB, x1, cacc2[1*4+1]);
            FMA2(cacc2[1*4+2], wB, x2, cacc2[1*4+2]);
            FMA2(cacc2[1*4+3], wB, x3, cacc2[1*4+3]);
            FMA2(cacc2[2*4+0], wC, x0, cacc2[2*4+0]);
            FMA2(cacc2[2*4+1], wC, x1, cacc2[2*4+1]);
            FMA2(cacc2[2*4+2], wC, x2, cacc2[2*4+2]);
            FMA2(cacc2[2*4+3], wC, x3, cacc2[2*4+3]);
        }
    }
    float cacc[24];
#pragma unroll
    for (int q2 = 0; q2 < 3; q2++) {
#pragma unroll
        for (int rho = 0; rho < 4; rho++) {
            float lo, hi;
            upk2(lo, hi, cacc2[q2*4+rho]);
            cacc[(2*q2)*4   + rho] = lo;
            cacc[(2*q2+1)*4 + rho] = hi;
        }
    }
    float lg[12];
#pragma unroll
    for (int i = 0; i < 12; i++) lg[i] = 0.f;
#pragma unroll
    for (int q = 0; q < 6; q++) {
        int j = g*6 + q;
        float w0 = sm[S3_WC2 + j];
        float w1 = sm[S3_WC2 + 48 + j];
        float w2 = sm[S3_WC2 + 96 + j];
#pragma unroll
        for (int rho = 0; rho < 4; rho++) {
            float a = fmaxf(cacc[q*4+rho], 0.f);
            lg[0*4+rho] = fmaf(a, w0, lg[0*4+rho]);
            lg[1*4+rho] = fmaf(a, w1, lg[1*4+rho]);
            lg[2*4+rho] = fmaf(a, w2, lg[2*4+rho]);
        }
    }
#pragma unroll
    for (int m = 4; m < 32; m <<= 1)
#pragma unroll
        for (int i = 0; i < 12; i++)
            lg[i] += __shfl_xor_sync(0xffffffffu, lg[i], m);
    float bc20 = sm[S3_BC2+0], bc21 = sm[S3_BC2+1], bc22 = sm[S3_BC2+2];
#pragma unroll
    for (int rho = 0; rho < 4; rho++) {
        float l0 = lg[rho] + bc20, l1 = lg[4+rho] + bc21, l2 = lg[8+rho] + bc22;
        float mm = fmaxf(l0, fmaxf(l1, l2));
        float e0 = __expf(l0 - mm), e1 = __expf(l1 - mm), e2 = __expf(l2 - mm);
        float inv = __frcp_rn(e0 + e1 + e2);
        int row = row0 + rbase + rho;
        if (row < nr && g < 3) {
            float e = (g == 0) ? e0 : (g == 1) ? e1 : e2;
            out[(size_t)row * 3 + g] = e * inv;
        }
    }
}

// ===========================================================================
extern "C" void kernel_launch(void* const* d_in, const int* in_sizes, int n_in,
                              void* d_out, int out_size)
{
    const float* A[24];
    for (int i = 0; i < 24; i++) A[i] = (const float*)d_in[i];

    int nr = in_sizes[0] / 90;
    if (nr > NRMAX) nr = NRMAX;

    float *qt, *kt, *vt, *mid, *MT;
    cudaGetSymbolAddress((void**)&qt,  g_qt);
    cudaGetSymbolAddress((void**)&kt,  g_kt);
    cudaGetSymbolAddress((void**)&vt,  g_vt);
    cudaGetSymbolAddress((void**)&mid, g_mid);
    cudaGetSymbolAddress((void**)&MT,  g_MT);

    k_precompute<<<1, 128>>>(A[3], A[4], MT);

    int btr = (nr + 31) / 32;
    dim3 g0(btr, 3);
    k_transpose3<<<g0, 256>>>(A[0], A[1], A[2], qt, kt, vt, nr);

    int bx = (nr + 255) / 256;
    dim3 g1(bx, 3);
    k_phase12<<<g1, 256>>>(qt, kt, vt,
                           MT, A[5],
                           A[6], A[7],
                           A[8], A[9], A[10], A[11],
                           A[12], A[13],
                           mid, nr);

    int bx3 = (nr + 127) / 128;
    cudaFuncSetAttribute(k_phase3, cudaFuncAttributeMaxDynamicSharedMemorySize,
                         S3_TOT * (int)sizeof(float));
    k_phase3<<<bx3, NT3, S3_TOT * sizeof(float)>>>(
        mid,
        A[14], A[15], A[16], A[17],
        A[18], A[19],
        A[20], A[21], A[22], A[23],
        (float*)d_out, nr);
}